// round 9
// baseline (speedup 1.0000x reference)
#include <cuda_runtime.h>
#include <math.h>

#define NNODES 100000
#define BATCH  4096
#define MDIM   256
#define G3DIM  768
#define INENC  515
#define NT     512
#define BK     16
#define PREF   4

typedef unsigned long long u64;

// ---------------- device scratch (rebuilt every launch; graph-replay safe) -----------
__device__ int      g_ncnt[NNODES];
__device__ int      g_nbuck[NNODES * BK];
__device__ int      g_pred[2 * BATCH];
__device__ float    g_F[2 * BATCH];
__device__ int      g_evlist[BATCH];
__device__ int      g_lvl_start[BATCH + 2];
__device__ int      g_nlevels;
__device__ unsigned g_bar_count = 0;
__device__ unsigned g_bar_gen   = 0;

__device__ int   g_pS[BATCH], g_pD[BATCH];
__device__ float g_pFs[BATCH], g_pFd[BATCH];
__device__ float g_pEF[BATCH * 3];

__device__ __align__(16) float g_H1 [BATCH * MDIM];
__device__ __align__(16) float g_GI [BATCH * G3DIM];
__device__ __align__(16) float g_GHs[BATCH * G3DIM];
__device__ __align__(16) float g_GHd[BATCH * G3DIM];

// transposed+packed weights: layout [k4][c][4] (16B per (k4,c))
__device__ __align__(16) float g_W1tA[MDIM * MDIM];
__device__ __align__(16) float g_W1tB[MDIM * MDIM];
__device__ __align__(16) float g_W1te[3 * MDIM];
__device__ __align__(16) float g_whht[G3DIM * MDIM];
__device__ __align__(16) float g_Wct [G3DIM * MDIM];
__device__ __align__(16) float g_bc  [G3DIM];

// ---------------- software grid barrier (all CTAs resident by construction) ----------
__device__ __forceinline__ void grid_sync() {
    __syncthreads();
    if (threadIdx.x == 0) {
        __threadfence();
        unsigned gen = *((volatile unsigned*)&g_bar_gen);
        if (atomicAdd(&g_bar_count, 1u) == gridDim.x - 1u) {
            *((volatile unsigned*)&g_bar_count) = 0u;
            __threadfence();
            atomicAdd(&g_bar_gen, 1u);
        } else {
            while (*((volatile unsigned*)&g_bar_gen) == gen) { __nanosleep(64); }
        }
        __threadfence();
    }
    __syncthreads();
}

// ---------------- packed f32x2 + cp.async helpers -------------------------------------
__device__ __forceinline__ u64 ffma2(u64 a, u64 b, u64 c) {
    u64 d;
    asm("fma.rn.f32x2 %0, %1, %2, %3;" : "=l"(d) : "l"(a), "l"(b), "l"(c));
    return d;
}
__device__ __forceinline__ float pair_sum(u64 v) {
    float lo, hi;
    asm("mov.b64 {%0, %1}, %2;" : "=f"(lo), "=f"(hi) : "l"(v));
    return lo + hi;
}
__device__ __forceinline__ unsigned s2u(const void* p) {
    unsigned a;
    asm("{ .reg .u64 t; cvta.to.shared.u64 t, %1; cvt.u32.u64 %0, t; }" : "=r"(a) : "l"(p));
    return a;
}
#define CP_A16(dst, src) \
    asm volatile("cp.async.cg.shared.global [%0], [%1], 16;" :: "r"(dst), "l"(src))
#define CP_COMMIT() asm volatile("cp.async.commit_group;" ::: "memory")
#define CP_WAIT3()  asm volatile("cp.async.wait_group 3;"  ::: "memory")

// ---------------- shared memory layouts ----------------------------------------------
struct __align__(16) TileSm {
    float Xa[8][MDIM];
    float Xb[8][MDIM];
    float EF[8][4];
};
struct __align__(16) SmAll {
    TileSm tile;
    ulonglong2 wbuf[PREF][NT][2];   // per-thread weight pipeline stages (64 KB)
};
struct LvlS {
    int level[BATCH];
    int off[BATCH + 2];
    int cnt[BATCH + 2];
    int maxl;
    int changed;
};
#define SMEM_BYTES ((int)(sizeof(LvlS) > sizeof(SmAll) ? sizeof(LvlS) : sizeof(SmAll)))

extern __shared__ __align__(16) char smem_raw[];

__device__ __forceinline__ float sigmoidf_(float x) { return 1.0f / (1.0f + expf(-x)); }

// ---------------- per-level phase-parallel pipeline ----------------------------------
// R rows per 256-thread group; tile height TMR = 2*R (<= 8).
template<int R>
__device__ void run_level(int lvS, int lvE,
                          const float* __restrict__ b1,
                          const float* __restrict__ bhh,
                          float* __restrict__ out)
{
    const int TMR = 2 * R;
    const int tid = threadIdx.x;
    const int nE = lvE - lvS;
    const int nchunk = (nE + TMR - 1) / TMR;
    SmAll* Sm = (SmAll*)smem_raw;
    TileSm* Sx = &Sm->tile;
    const ulonglong2* w1a2 = (const ulonglong2*)g_W1tA;
    const ulonglong2* w1b2 = (const ulonglong2*)g_W1tB;
    const ulonglong2* whh2 = (const ulonglong2*)g_whht;
    const ulonglong2* wct2 = (const ulonglong2*)g_Wct;
    const unsigned wb0 = s2u(&Sm->wbuf[0][tid][0]);
    const unsigned WST = NT * 32;   // bytes per pipeline stage

    // ---- P1: 2 units per chunk.  type 0: H1.  type 1: all 3 GH col-blocks (src+dst)
    for (int u = blockIdx.x; u < 2 * nchunk; u += gridDim.x) {
        int chunk = u >> 1, type = u & 1;
        int base = lvS + chunk * TMR;
        int cnt = min(TMR, lvE - base);
        __syncthreads();
        // gather decayed Xs -> Xa, Xd -> Xb
        for (int i = tid; i < TMR * MDIM; i += NT) {
            int m = i >> 8, c = i & 255;
            float xs = 0.f, xd = 0.f;
            if (m < cnt) {
                int p = base + m;
                xs = out[(size_t)g_pS[p] * MDIM + c] * g_pFs[p];
                xd = out[(size_t)g_pD[p] * MDIM + c] * g_pFd[p];
            }
            Sx->Xa[m][c] = xs;
            Sx->Xb[m][c] = xd;
        }
        if (type == 0 && tid < TMR) {
            int m = tid;
            float e0 = 0.f, e1 = 0.f, e2 = 0.f;
            if (m < cnt) {
                int p = base + m;
                e0 = g_pEF[3 * p]; e1 = g_pEF[3 * p + 1]; e2 = g_pEF[3 * p + 2];
            }
            Sx->EF[m][0] = e0; Sx->EF[m][1] = e1; Sx->EF[m][2] = e2; Sx->EF[m][3] = 0.f;
        }
        __syncthreads();

        int c = tid & 255, m0 = (tid >> 8) * R;

        if (type == 0) {
            const ulonglong2* sA = w1a2 + c;
            const ulonglong2* sB = w1b2 + c;
            #pragma unroll
            for (int s = 0; s < PREF; s++) {
                CP_A16(wb0 + s * WST,      sA + (size_t)s * MDIM);
                CP_A16(wb0 + s * WST + 16, sB + (size_t)s * MDIM);
                CP_COMMIT();
            }
            u64 acc[R];
            #pragma unroll
            for (int r = 0; r < R; r++) acc[r] = 0ull;
            for (int k4 = 0; k4 < 64; k4++) {
                CP_WAIT3();
                int st = k4 & (PREF - 1);
                ulonglong2 wA = Sm->wbuf[st][tid][0];
                ulonglong2 wB = Sm->wbuf[st][tid][1];
                #pragma unroll
                for (int r = 0; r < R; r++) {
                    ulonglong2 xa = ((const ulonglong2*)Sx->Xa[m0 + r])[k4];
                    ulonglong2 xb = ((const ulonglong2*)Sx->Xb[m0 + r])[k4];
                    acc[r] = ffma2(xa.x, wA.x, acc[r]);
                    acc[r] = ffma2(xa.y, wA.y, acc[r]);
                    acc[r] = ffma2(xb.x, wB.x, acc[r]);
                    acc[r] = ffma2(xb.y, wB.y, acc[r]);
                }
                int kn = k4 + PREF;
                if (kn < 64) {
                    CP_A16(wb0 + st * WST,      sA + (size_t)kn * MDIM);
                    CP_A16(wb0 + st * WST + 16, sB + (size_t)kn * MDIM);
                }
                CP_COMMIT();
            }
            float w0 = g_W1te[c], w1 = g_W1te[MDIM + c], w2 = g_W1te[2 * MDIM + c];
            float bb = b1[c];
            #pragma unroll
            for (int r = 0; r < R; r++) {
                float a = pair_sum(acc[r]) + bb;
                a = fmaf(Sx->EF[m0 + r][0], w0, a);
                a = fmaf(Sx->EF[m0 + r][1], w1, a);
                a = fmaf(Sx->EF[m0 + r][2], w2, a);
                if (m0 + r < cnt)
                    g_H1[(size_t)(base + m0 + r) * MDIM + c] = fmaxf(a, 0.f);
            }
        } else {
            // GH: 3 col-blocks, flat 192-stage pipeline over (cb, k4)
            #pragma unroll
            for (int s = 0; s < PREF; s++) {
                CP_A16(wb0 + s * WST, whh2 + (size_t)s * G3DIM + c);
                CP_COMMIT();
            }
            for (int cb = 0; cb < 3; cb++) {
                u64 accS[R], accD[R];
                #pragma unroll
                for (int r = 0; r < R; r++) { accS[r] = 0ull; accD[r] = 0ull; }
                for (int k4 = 0; k4 < 64; k4++) {
                    CP_WAIT3();
                    int s = cb * 64 + k4;
                    int st = s & (PREF - 1);
                    ulonglong2 w = Sm->wbuf[st][tid][0];
                    #pragma unroll
                    for (int r = 0; r < R; r++) {
                        ulonglong2 xa = ((const ulonglong2*)Sx->Xa[m0 + r])[k4];
                        ulonglong2 xb = ((const ulonglong2*)Sx->Xb[m0 + r])[k4];
                        accS[r] = ffma2(xa.x, w.x, accS[r]);
                        accS[r] = ffma2(xa.y, w.y, accS[r]);
                        accD[r] = ffma2(xb.x, w.x, accD[r]);
                        accD[r] = ffma2(xb.y, w.y, accD[r]);
                    }
                    int sn = s + PREF;
                    if (sn < 192) {
                        int kb = sn & 63, cbn = sn >> 6;
                        CP_A16(wb0 + st * WST,
                               whh2 + (size_t)kb * G3DIM + cbn * MDIM + c);
                    }
                    CP_COMMIT();
                }
                int ccol = cb * MDIM + c;
                float bb = bhh[ccol];
                #pragma unroll
                for (int r = 0; r < R; r++) {
                    if (m0 + r < cnt) {
                        g_GHs[(size_t)(base + m0 + r) * G3DIM + ccol] = pair_sum(accS[r]) + bb;
                        g_GHd[(size_t)(base + m0 + r) * G3DIM + ccol] = pair_sum(accD[r]) + bb;
                    }
                }
            }
        }
    }
    grid_sync();

    // ---- P2: GI = H1 @ Wc^T + bc  (3 col-blocks per chunk, pipelined weights)
    for (int u = blockIdx.x; u < 3 * nchunk; u += gridDim.x) {
        int chunk = u / 3, cb = u - chunk * 3;
        int base = lvS + chunk * TMR;
        int cnt = min(TMR, lvE - base);
        __syncthreads();
        for (int i = tid; i < TMR * MDIM; i += NT) {
            int m = i >> 8, c = i & 255;
            Sx->Xa[m][c] = (m < cnt) ? g_H1[(size_t)(base + m) * MDIM + c] : 0.f;
        }
        __syncthreads();
        int cl = tid & 255, m0 = (tid >> 8) * R;
        int c = cb * MDIM + cl;
        const ulonglong2* sW = wct2 + c;
        #pragma unroll
        for (int s = 0; s < PREF; s++) {
            CP_A16(wb0 + s * WST, sW + (size_t)s * G3DIM);
            CP_COMMIT();
        }
        u64 acc[R];
        #pragma unroll
        for (int r = 0; r < R; r++) acc[r] = 0ull;
        for (int k4 = 0; k4 < 64; k4++) {
            CP_WAIT3();
            int st = k4 & (PREF - 1);
            ulonglong2 w = Sm->wbuf[st][tid][0];
            #pragma unroll
            for (int r = 0; r < R; r++) {
                ulonglong2 x = ((const ulonglong2*)Sx->Xa[m0 + r])[k4];
                acc[r] = ffma2(x.x, w.x, acc[r]);
                acc[r] = ffma2(x.y, w.y, acc[r]);
            }
            int kn = k4 + PREF;
            if (kn < 64) CP_A16(wb0 + st * WST, sW + (size_t)kn * G3DIM);
            CP_COMMIT();
        }
        float bb = g_bc[c];
        #pragma unroll
        for (int r = 0; r < R; r++)
            if (m0 + r < cnt)
                g_GI[(size_t)(base + m0 + r) * G3DIM + c] = pair_sum(acc[r]) + bb;
    }
    grid_sync();

    // ---- P3: GRU elementwise + scatter
    for (int idx = blockIdx.x * NT + tid; idx < nE * MDIM; idx += gridDim.x * NT) {
        int pl = idx >> 8, j = idx & 255;
        int p = lvS + pl;
        int s = g_pS[p], d = g_pD[p];
        float hs = out[(size_t)s * MDIM + j] * g_pFs[p];
        float hd = out[(size_t)d * MDIM + j] * g_pFd[p];
        const float* gi  = g_GI  + (size_t)p * G3DIM;
        const float* ghs = g_GHs + (size_t)p * G3DIM;
        const float* ghd = g_GHd + (size_t)p * G3DIM;
        float gir = gi[j], giz = gi[MDIM + j], gin = gi[2 * MDIM + j];
        float rr = sigmoidf_(gir + ghs[j]);
        float zz = sigmoidf_(giz + ghs[MDIM + j]);
        float nn = tanhf(gin + rr * ghs[2 * MDIM + j]);
        float us = (1.0f - zz) * nn + zz * hs;
        rr = sigmoidf_(gir + ghd[j]);
        zz = sigmoidf_(giz + ghd[MDIM + j]);
        nn = tanhf(gin + rr * ghd[2 * MDIM + j]);
        float ud = (1.0f - zz) * nn + zz * hd;
        if (s != d) out[(size_t)s * MDIM + j] = us;   // dst wins when s==d
        out[(size_t)d * MDIM + j] = ud;
    }
    grid_sync();
}

__global__ void __launch_bounds__(NT, 2)
tgn_kernel(const int* __restrict__ src, const int* __restrict__ dst,
           const float* __restrict__ ef, const int* __restrict__ ts,
           const float* __restrict__ mem0, const float* __restrict__ lu0,
           const float* __restrict__ W1, const float* __restrict__ b1,
           const float* __restrict__ W2, const float* __restrict__ b2,
           const float* __restrict__ wih, const float* __restrict__ bih,
           const float* __restrict__ whh, const float* __restrict__ bhh,
           float* __restrict__ out)
{
    const int tid     = threadIdx.x;
    const int gtid    = blockIdx.x * NT + tid;
    const int gstride = gridDim.x * NT;

    // ---------- Phase A: copy memory -> out; weight transforms; counters -------------
    {
        const float4* s4 = (const float4*)mem0;
        float4*       d4 = (float4*)out;
        const int n4 = NNODES * MDIM / 4;
        for (int i = gtid; i < n4; i += gstride) d4[i] = s4[i];
        for (int i = gtid; i < NNODES; i += gstride) g_ncnt[i] = 0;

        for (int i = gtid; i < MDIM * MDIM; i += gstride) {
            int k4 = i >> 10, rem = i & 1023, c = rem >> 2, ks = rem & 3;
            int k = k4 * 4 + ks;
            g_W1tA[i] = W1[(size_t)c * INENC + k];
            g_W1tB[i] = W1[(size_t)c * INENC + MDIM + k];
        }
        for (int i = gtid; i < G3DIM * MDIM; i += gstride) {
            int k4 = i / 3072, rem = i - k4 * 3072, c = rem >> 2, ks = rem & 3;
            int k = k4 * 4 + ks;
            g_whht[i] = whh[(size_t)c * MDIM + k];
        }
        for (int i = gtid; i < 3 * MDIM; i += gstride) {
            int k = i >> 8, c = i & 255;
            g_W1te[i] = W1[(size_t)c * INENC + 2 * MDIM + k];
        }
        // Wc = wih @ W2 (packed), bc = bih + wih @ b2
        for (int i = gtid; i < G3DIM * (MDIM / 4); i += gstride) {
            int c = i >> 6, k4 = i & 63;
            float4 a = make_float4(0.f, 0.f, 0.f, 0.f);
            const float*  wr  = wih + (size_t)c * MDIM;
            const float4* w2r = (const float4*)W2;
            for (int j = 0; j < MDIM; j++) {
                float wv = wr[j];
                float4 b = w2r[j * 64 + k4];
                a.x = fmaf(wv, b.x, a.x);
                a.y = fmaf(wv, b.y, a.y);
                a.z = fmaf(wv, b.z, a.z);
                a.w = fmaf(wv, b.w, a.w);
            }
            float* dstp = g_Wct + (size_t)k4 * 3072 + c * 4;
            dstp[0] = a.x; dstp[1] = a.y; dstp[2] = a.z; dstp[3] = a.w;
        }
        for (int c = gtid; c < G3DIM; c += gstride) {
            float acc = bih[c];
            const float* wr = wih + (size_t)c * MDIM;
            for (int j = 0; j < MDIM; j++) acc = fmaf(wr[j], b2[j], acc);
            g_bc[c] = acc;
        }
    }
    grid_sync();

    // ---------- Phase A2: per-node occurrence buckets ---------------------------------
    for (int i = gtid; i < 2 * BATCH; i += gstride) {
        int e = i >> 1;
        int v = (i & 1) ? dst[e] : src[e];
        int slot = atomicAdd(&g_ncnt[v], 1);
        if (slot < BK) g_nbuck[v * BK + slot] = i;
    }
    grid_sync();

    // ---------- Phase A3: predecessor endpoint + decay factor -------------------------
    for (int i = gtid; i < 2 * BATCH; i += gstride) {
        int e = i >> 1;
        int v = (i & 1) ? dst[e] : src[e];
        int lim = e << 1;
        int cmax = min(g_ncnt[v], BK);
        int p = -1;
        for (int t = 0; t < cmax; t++) {
            int j = g_nbuck[v * BK + t];
            if (j < lim && j > p) p = j;
        }
        g_pred[i] = p;
        float prev_t = (p >= 0) ? (float)ts[p >> 1] : lu0[v];
        float dt = fmaxf((float)ts[e] - prev_t, 0.f);
        g_F[i] = expf(-0.1f * dt);
    }
    grid_sync();

    // ---------- Phase B (block 0): levelize + sort + permuted metadata ----------------
    if (blockIdx.x == 0) {
        LvlS* L = (LvlS*)smem_raw;
        for (int e = tid; e < BATCH; e += NT) L->level[e] = 0;
        if (tid == 0) L->maxl = 0;
        __syncthreads();
        for (;;) {
            if (tid == 0) L->changed = 0;
            __syncthreads();
            for (int e = tid; e < BATCH; e += NT) {
                int ps = g_pred[2 * e], pd = g_pred[2 * e + 1];
                int lv = 0;
                if (ps >= 0) { int t = L->level[ps >> 1] + 1; if (t > lv) lv = t; }
                if (pd >= 0) { int t = L->level[pd >> 1] + 1; if (t > lv) lv = t; }
                if (lv > L->level[e]) { L->level[e] = lv; L->changed = 1; }
            }
            __syncthreads();
            int ch = L->changed;
            __syncthreads();
            if (!ch) break;
        }
        for (int e = tid; e < BATCH; e += NT) atomicMax(&L->maxl, L->level[e]);
        __syncthreads();
        int nl = L->maxl + 1;
        for (int i = tid; i < nl + 1; i += NT) L->cnt[i] = 0;
        __syncthreads();
        for (int e = tid; e < BATCH; e += NT) atomicAdd(&L->cnt[L->level[e]], 1);
        __syncthreads();
        if (tid == 0) {
            int acc = 0;
            for (int l = 0; l < nl; l++) { L->off[l] = acc; acc += L->cnt[l]; }
            L->off[nl] = acc;
            g_nlevels = nl;
            for (int l = 0; l <= nl; l++) g_lvl_start[l] = L->off[l];
        }
        __syncthreads();
        for (int i = tid; i < nl; i += NT) L->cnt[i] = 0;
        __syncthreads();
        for (int e = tid; e < BATCH; e += NT) {
            int l = L->level[e];
            int pos = L->off[l] + atomicAdd(&L->cnt[l], 1);
            g_evlist[pos] = e;
        }
        __syncthreads();
        for (int p = tid; p < BATCH; p += NT) {
            int e = g_evlist[p];
            g_pS[p] = src[e];
            g_pD[p] = dst[e];
            g_pFs[p] = g_F[2 * e];
            g_pFd[p] = g_F[2 * e + 1];
            g_pEF[3 * p]     = ef[3 * e];
            g_pEF[3 * p + 1] = ef[3 * e + 1];
            g_pEF[3 * p + 2] = ef[3 * e + 2];
        }
    }
    grid_sync();

    // ---------- Phase C: per-level phase-parallel pipeline ----------------------------
    const int nlevels = g_nlevels;
    for (int lvl = 0; lvl < nlevels; lvl++) {
        int lvS = g_lvl_start[lvl];
        int lvE = g_lvl_start[lvl + 1];
        if (lvE - lvS <= 64) run_level<1>(lvS, lvE, b1, bhh, out);
        else                 run_level<4>(lvS, lvE, b1, bhh, out);
    }
}

extern "C" void kernel_launch(void* const* d_in, const int* in_sizes, int n_in,
                              void* d_out, int out_size)
{
    const int*   src  = (const int*)  d_in[0];
    const int*   dst  = (const int*)  d_in[1];
    const float* ef   = (const float*)d_in[2];
    const int*   ts   = (const int*)  d_in[3];
    const float* mem0 = (const float*)d_in[4];
    const float* lu0  = (const float*)d_in[5];
    const float* W1   = (const float*)d_in[6];
    const float* b1   = (const float*)d_in[7];
    const float* W2   = (const float*)d_in[8];
    const float* b2   = (const float*)d_in[9];
    const float* wih  = (const float*)d_in[10];
    const float* whh  = (const float*)d_in[11];
    const float* bih  = (const float*)d_in[12];
    const float* bhh  = (const float*)d_in[13];
    float* out = (float*)d_out;

    int dev = 0, sms = 148;
    cudaGetDevice(&dev);
    cudaDeviceGetAttribute(&sms, cudaDevAttrMultiProcessorCount, dev);
    if (sms <= 0) sms = 148;

    cudaFuncSetAttribute(tgn_kernel, cudaFuncAttributeMaxDynamicSharedMemorySize, SMEM_BYTES);

    // Deadlock-proof grid sizing: only launch as many CTAs as are guaranteed
    // co-resident (the software grid barrier requires full residency).
    int occ = 0;
    cudaOccupancyMaxActiveBlocksPerMultiprocessor(&occ, tgn_kernel, NT, SMEM_BYTES);
    if (occ < 1) occ = 1;
    if (occ > 2) occ = 2;

    tgn_kernel<<<occ * sms, NT, SMEM_BYTES>>>(src, dst, ef, ts, mem0, lu0,
                                              W1, b1, W2, b2, wih, bih, whh, bhh, out);
}

// round 10
// speedup vs baseline: 1.8938x; 1.8938x over previous
#include <cuda_runtime.h>
#include <math.h>

#define NNODES 100000
#define BATCH  4096
#define MDIM   256
#define G3DIM  768
#define INENC  515
#define NT     512
#define BK     16

typedef unsigned long long u64;

// ---------------- device scratch (rebuilt every launch; graph-replay safe) -----------
__device__ int      g_ncnt[NNODES];
__device__ int      g_nbuck[NNODES * BK];
__device__ int      g_pred[2 * BATCH];
__device__ float    g_F[2 * BATCH];
__device__ int      g_evlist[BATCH];
__device__ int      g_lvl_start[BATCH + 2];
__device__ int      g_nlevels;
__device__ unsigned g_bar_count = 0;
__device__ unsigned g_bar_gen   = 0;

__device__ int   g_pS[BATCH], g_pD[BATCH];
__device__ float g_pFs[BATCH], g_pFd[BATCH];
__device__ float g_pEF[BATCH * 3];

// transposed+packed weights: layout [k4][c][4] (16B per (k4,c))
__device__ __align__(16) float g_W1tA[MDIM * MDIM];
__device__ __align__(16) float g_W1tB[MDIM * MDIM];
__device__ __align__(16) float g_W1te[3 * MDIM];
__device__ __align__(16) float g_whht[G3DIM * MDIM];
__device__ __align__(16) float g_Wct [G3DIM * MDIM];
__device__ __align__(16) float g_bc  [G3DIM];

// ---------------- software grid barrier (all CTAs resident by construction) ----------
__device__ __forceinline__ void grid_sync() {
    __syncthreads();
    if (threadIdx.x == 0) {
        __threadfence();
        unsigned gen = *((volatile unsigned*)&g_bar_gen);
        if (atomicAdd(&g_bar_count, 1u) == gridDim.x - 1u) {
            *((volatile unsigned*)&g_bar_count) = 0u;
            __threadfence();
            atomicAdd(&g_bar_gen, 1u);
        } else {
            while (*((volatile unsigned*)&g_bar_gen) == gen) { __nanosleep(64); }
        }
        __threadfence();
    }
    __syncthreads();
}

// ---------------- packed f32x2 helpers ------------------------------------------------
__device__ __forceinline__ u64 ffma2(u64 a, u64 b, u64 c) {
    u64 d;
    asm("fma.rn.f32x2 %0, %1, %2, %3;" : "=l"(d) : "l"(a), "l"(b), "l"(c));
    return d;
}
__device__ __forceinline__ float pair_sum(u64 v) {
    float lo, hi;
    asm("mov.b64 {%0, %1}, %2;" : "=f"(lo), "=f"(hi) : "l"(v));
    return lo + hi;
}

// ---------------- shared memory ------------------------------------------------------
#define TMR_BIG 14
#define CH_SMEM(T) ((T) * (3 * MDIM + 3 * G3DIM + 4) * 4)
struct LvlS {
    int level[BATCH];
    int off[BATCH + 2];
    int cnt[BATCH + 2];
    int maxl;
    int changed;
};
#define SMEM_BYTES ((int)(sizeof(LvlS) > CH_SMEM(TMR_BIG) ? sizeof(LvlS) : CH_SMEM(TMR_BIG)))

extern __shared__ __align__(16) char smem_raw[];

__device__ __forceinline__ float sigmoidf_(float x) { return 1.0f / (1.0f + expf(-x)); }

// ---------------- fully fused per-chunk level processing ------------------------------
// One unit per chunk of TMR events: gather -> H1 -> GI -> GH -> GRU -> scatter.
// One grid_sync per level.
template<int TMR>
__device__ void run_level(int lvS, int lvE,
                          const float* __restrict__ b1,
                          const float* __restrict__ bhh,
                          float* __restrict__ out)
{
    const int tid = threadIdx.x;
    const int nE = lvE - lvS;
    const int nchunk = (nE + TMR - 1) / TMR;

    float* Xa  = (float*)smem_raw;        // [TMR][256] decayed src state
    float* Xb  = Xa  + TMR * MDIM;        // [TMR][256] decayed dst state
    float* H1s = Xb  + TMR * MDIM;        // [TMR][256] H1 (also A-partial)
    float* GIs = H1s + TMR * MDIM;        // [TMR][768] GI (also B-partial temp)
    float* GHs = GIs + TMR * G3DIM;       // [TMR][768]
    float* GHd = GHs + TMR * G3DIM;       // [TMR][768]
    float* EFs = GHd + TMR * G3DIM;       // [TMR][4]

    const ulonglong2* w1a2 = (const ulonglong2*)g_W1tA;
    const ulonglong2* w1b2 = (const ulonglong2*)g_W1tB;
    const ulonglong2* whh2 = (const ulonglong2*)g_whht;
    const ulonglong2* wct2 = (const ulonglong2*)g_Wct;

    for (int chunk = blockIdx.x; chunk < nchunk; chunk += gridDim.x) {
        const int base = lvS + chunk * TMR;
        const int cnt  = min(TMR, lvE - base);
        __syncthreads();   // protect smem from previous chunk's readers

        // ---- gather decayed states + edge features
        for (int i = tid; i < TMR * MDIM; i += NT) {
            int m = i >> 8, c = i & 255;
            float xs = 0.f, xd = 0.f;
            if (m < cnt) {
                int p = base + m;
                xs = out[(size_t)g_pS[p] * MDIM + c] * g_pFs[p];
                xd = out[(size_t)g_pD[p] * MDIM + c] * g_pFd[p];
            }
            Xa[i] = xs;
            Xb[i] = xd;
        }
        if (tid < TMR) {
            float e0 = 0.f, e1 = 0.f, e2 = 0.f;
            if (tid < cnt) {
                int p = base + tid;
                e0 = g_pEF[3 * p]; e1 = g_pEF[3 * p + 1]; e2 = g_pEF[3 * p + 2];
            }
            EFs[tid * 4] = e0; EFs[tid * 4 + 1] = e1;
            EFs[tid * 4 + 2] = e2; EFs[tid * 4 + 3] = 0.f;
        }
        __syncthreads();

        // ---- H1 partials: k-split across the two 256-thread groups
        {
            int c = tid & 255, g = tid >> 8;
            const ulonglong2* W = g ? w1b2 : w1a2;
            const float* X = g ? Xb : Xa;
            float* Hp = g ? GIs : H1s;          // B-partial parked in GIs temporarily
            u64 acc[TMR];
            #pragma unroll
            for (int r = 0; r < TMR; r++) acc[r] = 0ull;
            #pragma unroll 2
            for (int k4 = 0; k4 < 64; k4++) {
                ulonglong2 w = W[k4 * MDIM + c];
                #pragma unroll
                for (int r = 0; r < TMR; r++) {
                    ulonglong2 x = ((const ulonglong2*)(X + r * MDIM))[k4];
                    acc[r] = ffma2(x.x, w.x, acc[r]);
                    acc[r] = ffma2(x.y, w.y, acc[r]);
                }
            }
            #pragma unroll
            for (int r = 0; r < TMR; r++) Hp[r * MDIM + c] = pair_sum(acc[r]);
        }
        __syncthreads();

        // ---- combine H1 = relu(A + B + ef·W1e + b1)   (c = i&255 is loop-invariant)
        {
            int c = tid & 255;
            float w0 = g_W1te[c], w1 = g_W1te[MDIM + c], w2 = g_W1te[2 * MDIM + c];
            float bb = b1[c];
            for (int i = tid; i < TMR * MDIM; i += NT) {
                int m = i >> 8;
                float a = H1s[i] + GIs[i] + bb;
                a = fmaf(EFs[m * 4],     w0, a);
                a = fmaf(EFs[m * 4 + 1], w1, a);
                a = fmaf(EFs[m * 4 + 2], w2, a);
                H1s[i] = fmaxf(a, 0.f);
            }
        }
        __syncthreads();

        // ---- GI = H1 @ Wc^T + bc  (768 cols over 2 col-waves; each col read once)
        #pragma unroll 1
        for (int wave = 0; wave < 2; wave++) {
            int col = wave ? (512 + tid) : tid;
            if (col < G3DIM) {
                u64 acc[TMR];
                #pragma unroll
                for (int r = 0; r < TMR; r++) acc[r] = 0ull;
                #pragma unroll 2
                for (int k4 = 0; k4 < 64; k4++) {
                    ulonglong2 w = wct2[k4 * G3DIM + col];
                    #pragma unroll
                    for (int r = 0; r < TMR; r++) {
                        ulonglong2 x = ((const ulonglong2*)(H1s + r * MDIM))[k4];
                        acc[r] = ffma2(x.x, w.x, acc[r]);
                        acc[r] = ffma2(x.y, w.y, acc[r]);
                    }
                }
                float bb = g_bc[col];
                #pragma unroll
                for (int r = 0; r < TMR; r++)
                    GIs[r * G3DIM + col] = pair_sum(acc[r]) + bb;
            }
        }

        // ---- GH (src+dst fused; same weight read serves both)
        #pragma unroll 1
        for (int wave = 0; wave < 2; wave++) {
            int col = wave ? (512 + tid) : tid;
            if (col < G3DIM) {
                u64 aS[TMR], aD[TMR];
                #pragma unroll
                for (int r = 0; r < TMR; r++) { aS[r] = 0ull; aD[r] = 0ull; }
                #pragma unroll 2
                for (int k4 = 0; k4 < 64; k4++) {
                    ulonglong2 w = whh2[k4 * G3DIM + col];
                    #pragma unroll
                    for (int r = 0; r < TMR; r++) {
                        ulonglong2 xa = ((const ulonglong2*)(Xa + r * MDIM))[k4];
                        ulonglong2 xb = ((const ulonglong2*)(Xb + r * MDIM))[k4];
                        aS[r] = ffma2(xa.x, w.x, aS[r]);
                        aS[r] = ffma2(xa.y, w.y, aS[r]);
                        aD[r] = ffma2(xb.x, w.x, aD[r]);
                        aD[r] = ffma2(xb.y, w.y, aD[r]);
                    }
                }
                float bb = bhh[col];
                #pragma unroll
                for (int r = 0; r < TMR; r++) {
                    GHs[r * G3DIM + col] = pair_sum(aS[r]) + bb;
                    GHd[r * G3DIM + col] = pair_sum(aD[r]) + bb;
                }
            }
        }
        __syncthreads();

        // ---- GRU elementwise + scatter
        for (int i = tid; i < TMR * MDIM; i += NT) {
            int m = i >> 8, j = i & 255;
            if (m < cnt) {
                int p = base + m;
                int s = g_pS[p], d = g_pD[p];
                float hs = Xa[i], hd = Xb[i];
                const float* gi  = GIs + m * G3DIM;
                const float* ghs = GHs + m * G3DIM;
                const float* ghd = GHd + m * G3DIM;
                float gir = gi[j], giz = gi[MDIM + j], gin = gi[2 * MDIM + j];
                float rr = sigmoidf_(gir + ghs[j]);
                float zz = sigmoidf_(giz + ghs[MDIM + j]);
                float nn = tanhf(gin + rr * ghs[2 * MDIM + j]);
                float us = (1.0f - zz) * nn + zz * hs;
                rr = sigmoidf_(gir + ghd[j]);
                zz = sigmoidf_(giz + ghd[MDIM + j]);
                nn = tanhf(gin + rr * ghd[2 * MDIM + j]);
                float ud = (1.0f - zz) * nn + zz * hd;
                if (s != d) out[(size_t)s * MDIM + j] = us;   // dst wins when s==d
                out[(size_t)d * MDIM + j] = ud;
            }
        }
    }
    grid_sync();
}

__global__ void __launch_bounds__(NT, 1)
tgn_kernel(const int* __restrict__ src, const int* __restrict__ dst,
           const float* __restrict__ ef, const int* __restrict__ ts,
           const float* __restrict__ mem0, const float* __restrict__ lu0,
           const float* __restrict__ W1, const float* __restrict__ b1,
           const float* __restrict__ W2, const float* __restrict__ b2,
           const float* __restrict__ wih, const float* __restrict__ bih,
           const float* __restrict__ whh, const float* __restrict__ bhh,
           float* __restrict__ out)
{
    const int tid     = threadIdx.x;
    const int gtid    = blockIdx.x * NT + tid;
    const int gstride = gridDim.x * NT;

    // ---------- Phase A: copy memory -> out; weight transforms; counters -------------
    {
        const float4* s4 = (const float4*)mem0;
        float4*       d4 = (float4*)out;
        const int n4 = NNODES * MDIM / 4;
        for (int i = gtid; i < n4; i += gstride) d4[i] = s4[i];
        for (int i = gtid; i < NNODES; i += gstride) g_ncnt[i] = 0;

        for (int i = gtid; i < MDIM * MDIM; i += gstride) {
            int k4 = i >> 10, rem = i & 1023, c = rem >> 2, ks = rem & 3;
            int k = k4 * 4 + ks;
            g_W1tA[i] = W1[(size_t)c * INENC + k];
            g_W1tB[i] = W1[(size_t)c * INENC + MDIM + k];
        }
        for (int i = gtid; i < G3DIM * MDIM; i += gstride) {
            int k4 = i / 3072, rem = i - k4 * 3072, c = rem >> 2, ks = rem & 3;
            int k = k4 * 4 + ks;
            g_whht[i] = whh[(size_t)c * MDIM + k];
        }
        for (int i = gtid; i < 3 * MDIM; i += gstride) {
            int k = i >> 8, c = i & 255;
            g_W1te[i] = W1[(size_t)c * INENC + 2 * MDIM + k];
        }
        // Wc = wih @ W2 (packed), bc = bih + wih @ b2
        for (int i = gtid; i < G3DIM * (MDIM / 4); i += gstride) {
            int c = i >> 6, k4 = i & 63;
            float4 a = make_float4(0.f, 0.f, 0.f, 0.f);
            const float*  wr  = wih + (size_t)c * MDIM;
            const float4* w2r = (const float4*)W2;
            for (int j = 0; j < MDIM; j++) {
                float wv = wr[j];
                float4 b = w2r[j * 64 + k4];
                a.x = fmaf(wv, b.x, a.x);
                a.y = fmaf(wv, b.y, a.y);
                a.z = fmaf(wv, b.z, a.z);
                a.w = fmaf(wv, b.w, a.w);
            }
            float* dstp = g_Wct + (size_t)k4 * 3072 + c * 4;
            dstp[0] = a.x; dstp[1] = a.y; dstp[2] = a.z; dstp[3] = a.w;
        }
        for (int c = gtid; c < G3DIM; c += gstride) {
            float acc = bih[c];
            const float* wr = wih + (size_t)c * MDIM;
            for (int j = 0; j < MDIM; j++) acc = fmaf(wr[j], b2[j], acc);
            g_bc[c] = acc;
        }
    }
    grid_sync();

    // ---------- Phase A2: per-node occurrence buckets ---------------------------------
    for (int i = gtid; i < 2 * BATCH; i += gstride) {
        int e = i >> 1;
        int v = (i & 1) ? dst[e] : src[e];
        int slot = atomicAdd(&g_ncnt[v], 1);
        if (slot < BK) g_nbuck[v * BK + slot] = i;
    }
    grid_sync();

    // ---------- Phase A3: predecessor endpoint + decay factor -------------------------
    for (int i = gtid; i < 2 * BATCH; i += gstride) {
        int e = i >> 1;
        int v = (i & 1) ? dst[e] : src[e];
        int lim = e << 1;
        int cmax = min(g_ncnt[v], BK);
        int p = -1;
        for (int t = 0; t < cmax; t++) {
            int j = g_nbuck[v * BK + t];
            if (j < lim && j > p) p = j;
        }
        g_pred[i] = p;
        float prev_t = (p >= 0) ? (float)ts[p >> 1] : lu0[v];
        float dt = fmaxf((float)ts[e] - prev_t, 0.f);
        g_F[i] = expf(-0.1f * dt);
    }
    grid_sync();

    // ---------- Phase B (block 0): levelize + sort + permuted metadata ----------------
    if (blockIdx.x == 0) {
        LvlS* L = (LvlS*)smem_raw;
        for (int e = tid; e < BATCH; e += NT) L->level[e] = 0;
        if (tid == 0) L->maxl = 0;
        __syncthreads();
        for (;;) {
            if (tid == 0) L->changed = 0;
            __syncthreads();
            for (int e = tid; e < BATCH; e += NT) {
                int ps = g_pred[2 * e], pd = g_pred[2 * e + 1];
                int lv = 0;
                if (ps >= 0) { int t = L->level[ps >> 1] + 1; if (t > lv) lv = t; }
                if (pd >= 0) { int t = L->level[pd >> 1] + 1; if (t > lv) lv = t; }
                if (lv > L->level[e]) { L->level[e] = lv; L->changed = 1; }
            }
            __syncthreads();
            int ch = L->changed;
            __syncthreads();
            if (!ch) break;
        }
        for (int e = tid; e < BATCH; e += NT) atomicMax(&L->maxl, L->level[e]);
        __syncthreads();
        int nl = L->maxl + 1;
        for (int i = tid; i < nl + 1; i += NT) L->cnt[i] = 0;
        __syncthreads();
        for (int e = tid; e < BATCH; e += NT) atomicAdd(&L->cnt[L->level[e]], 1);
        __syncthreads();
        if (tid == 0) {
            int acc = 0;
            for (int l = 0; l < nl; l++) { L->off[l] = acc; acc += L->cnt[l]; }
            L->off[nl] = acc;
            g_nlevels = nl;
            for (int l = 0; l <= nl; l++) g_lvl_start[l] = L->off[l];
        }
        __syncthreads();
        for (int i = tid; i < nl; i += NT) L->cnt[i] = 0;
        __syncthreads();
        for (int e = tid; e < BATCH; e += NT) {
            int l = L->level[e];
            int pos = L->off[l] + atomicAdd(&L->cnt[l], 1);
            g_evlist[pos] = e;
        }
        __syncthreads();
        for (int p = tid; p < BATCH; p += NT) {
            int e = g_evlist[p];
            g_pS[p] = src[e];
            g_pD[p] = dst[e];
            g_pFs[p] = g_F[2 * e];
            g_pFd[p] = g_F[2 * e + 1];
            g_pEF[3 * p]     = ef[3 * e];
            g_pEF[3 * p + 1] = ef[3 * e + 1];
            g_pEF[3 * p + 2] = ef[3 * e + 2];
        }
    }
    grid_sync();

    // ---------- Phase C: fused per-level processing (one grid_sync per level) ---------
    const int nlevels = g_nlevels;
    for (int lvl = 0; lvl < nlevels; lvl++) {
        int lvS = g_lvl_start[lvl];
        int lvE = g_lvl_start[lvl + 1];
        if (lvE - lvS <= 64) run_level<2>(lvS, lvE, b1, bhh, out);
        else                 run_level<TMR_BIG>(lvS, lvE, b1, bhh, out);
    }
}

extern "C" void kernel_launch(void* const* d_in, const int* in_sizes, int n_in,
                              void* d_out, int out_size)
{
    const int*   src  = (const int*)  d_in[0];
    const int*   dst  = (const int*)  d_in[1];
    const float* ef   = (const float*)d_in[2];
    const int*   ts   = (const int*)  d_in[3];
    const float* mem0 = (const float*)d_in[4];
    const float* lu0  = (const float*)d_in[5];
    const float* W1   = (const float*)d_in[6];
    const float* b1   = (const float*)d_in[7];
    const float* W2   = (const float*)d_in[8];
    const float* b2   = (const float*)d_in[9];
    const float* wih  = (const float*)d_in[10];
    const float* whh  = (const float*)d_in[11];
    const float* bih  = (const float*)d_in[12];
    const float* bhh  = (const float*)d_in[13];
    float* out = (float*)d_out;

    int dev = 0, sms = 148;
    cudaGetDevice(&dev);
    cudaDeviceGetAttribute(&sms, cudaDevAttrMultiProcessorCount, dev);
    if (sms <= 0) sms = 148;

    cudaFuncSetAttribute(tgn_kernel, cudaFuncAttributeMaxDynamicSharedMemorySize, SMEM_BYTES);

    // Deadlock-proof grid sizing: software barrier requires full co-residency.
    int occ = 0;
    cudaOccupancyMaxActiveBlocksPerMultiprocessor(&occ, tgn_kernel, NT, SMEM_BYTES);
    if (occ < 1) occ = 1;
    if (occ > 2) occ = 2;

    tgn_kernel<<<occ * sms, NT, SMEM_BYTES>>>(src, dst, ef, ts, mem0, lu0,
                                              W1, b1, W2, b2, wih, bih, whh, bhh, out);
}